// round 2
// baseline (speedup 1.0000x reference)
#include <cuda_runtime.h>

#define NNODE 170
#define TSEQ  64
#define CIN   64
#define COUT  64
#define BATCH 32
#define NT    (NNODE*TSEQ)          // 10880
#define BSTRIDE (CIN*NT)            // 696320 (also COUT*NT for out)

// Scratch (allocation-free rule: __device__ globals)
__device__ float g_Y1[BATCH*CIN*NT];
__device__ float g_Y2[BATCH*CIN*NT];
__device__ float g_Wt[3*CIN*COUT];  // [k][c][o]

// ---------------------------------------------------------------------------
// Prep: transpose W[o, c*3+k] -> g_Wt[k][c][o]
// ---------------------------------------------------------------------------
__global__ void k_prep(const float* __restrict__ W)
{
    int i = blockIdx.x * 256 + threadIdx.x;   // 0 .. 12287
    if (i < 3*CIN*COUT) {
        int s = i / (CIN*COUT);
        int r = i % (CIN*COUT);
        int c = r / COUT;
        int o = r % COUT;
        g_Wt[i] = W[o*(3*CIN) + c*3 + s];
    }
}

// ---------------------------------------------------------------------------
// Node stage: per (b,c): Y1 = adj @ X,  Y2 = 2*adj @ Y1 - X   (node dim = 170)
// smem: adj padded to 176 rows (tail zeroed) + X + Y1 = 206,720 B (1 CTA/SM)
// ---------------------------------------------------------------------------
__global__ __launch_bounds__(256, 1) void k_node(const float* __restrict__ x,
                                                 const float* __restrict__ adj)
{
    extern __shared__ float sm[];
    float* s_adj = sm;                 // 176*170 floats
    float* s_X   = sm + 176*NNODE;     // 10880
    float* s_Y1  = s_X + NT;           // 10880

    const int tid = threadIdx.x;
    const int bc  = blockIdx.x;        // b*CIN + c
    const float* Xg = x + (size_t)bc * NT;
    float* Y1g = g_Y1 + (size_t)bc * NT;
    float* Y2g = g_Y2 + (size_t)bc * NT;

    // load adj (full matrix), zero the padded tail rows
    for (int i = tid; i < NNODE*NNODE; i += 256) s_adj[i] = adj[i];
    for (int i = NNODE*NNODE + tid; i < 176*NNODE; i += 256) s_adj[i] = 0.0f;
    // load X as float4
    {
        const float4* Xg4 = (const float4*)Xg;
        float4* sX4 = (float4*)s_X;
        for (int i = tid; i < NT/4; i += 256) sX4[i] = Xg4[i];
    }
    __syncthreads();

    const int tx = tid & 15;          // t4 block: t = tx*4 .. tx*4+3
    const int ty = tid >> 4;          // 0..15; q = ty + 16*j

    float4 acc[11];

    // ---- GEMM 1: Y1[q,t] = sum_n adj[q,n] * X[n,t] ----
    #pragma unroll
    for (int j = 0; j < 11; j++) acc[j] = make_float4(0.f, 0.f, 0.f, 0.f);

    #pragma unroll 2
    for (int n = 0; n < NNODE; n++) {
        const float4 xv = *(const float4*)(s_X + n*TSEQ + tx*4);
        #pragma unroll
        for (int j = 0; j < 11; j++) {
            const float a = s_adj[(ty + 16*j)*NNODE + n];
            acc[j].x += a * xv.x;
            acc[j].y += a * xv.y;
            acc[j].z += a * xv.z;
            acc[j].w += a * xv.w;
        }
    }
    #pragma unroll
    for (int j = 0; j < 11; j++) {
        const int q = ty + 16*j;
        if (q < NNODE) {
            *(float4*)(s_Y1 + q*TSEQ + tx*4) = acc[j];
            *(float4*)(Y1g  + q*TSEQ + tx*4) = acc[j];
        }
    }
    __syncthreads();

    // ---- GEMM 2: Y2[q,t] = 2*sum_n adj[q,n]*Y1[n,t] - X[q,t] ----
    #pragma unroll
    for (int j = 0; j < 11; j++) acc[j] = make_float4(0.f, 0.f, 0.f, 0.f);

    #pragma unroll 2
    for (int n = 0; n < NNODE; n++) {
        const float4 yv = *(const float4*)(s_Y1 + n*TSEQ + tx*4);
        #pragma unroll
        for (int j = 0; j < 11; j++) {
            const float a = s_adj[(ty + 16*j)*NNODE + n];
            acc[j].x += a * yv.x;
            acc[j].y += a * yv.y;
            acc[j].z += a * yv.z;
            acc[j].w += a * yv.w;
        }
    }
    #pragma unroll
    for (int j = 0; j < 11; j++) {
        const int q = ty + 16*j;
        if (q < NNODE) {
            const float4 xv = *(const float4*)(s_X + q*TSEQ + tx*4);
            float4 r;
            r.x = 2.f*acc[j].x - xv.x;
            r.y = 2.f*acc[j].y - xv.y;
            r.z = 2.f*acc[j].z - xv.z;
            r.w = 2.f*acc[j].w - xv.w;
            *(float4*)(Y2g + q*TSEQ + tx*4) = r;
        }
    }
}

// ---------------------------------------------------------------------------
// Channel stage: out[b,o,pos] = bias[o] + sum_{s,c} Wt[s][c][o]*src_s[b,c,pos]
// Tile: 64 o x 256 pos per CTA, thread = 8o x 8pos register block.
// ---------------------------------------------------------------------------
__global__ __launch_bounds__(256, 2) void k_chan(const float* __restrict__ x,
                                                 const float* __restrict__ bias,
                                                 float* __restrict__ out)
{
    __shared__ float s_in[16*256];   // [c][pos]
    __shared__ float s_W[16*COUT];   // [c][o]

    const int tid = threadIdx.x;
    const int b   = blockIdx.y;
    const int p0  = blockIdx.x * 256;
    const int og  = tid >> 5;        // 0..7
    const int pg  = tid & 31;        // 0..31
    const int o0  = og * 8;
    const int pl  = pg * 8;

    float acc[8][8];
    #pragma unroll
    for (int oi = 0; oi < 8; oi++)
        #pragma unroll
        for (int pi = 0; pi < 8; pi++)
            acc[oi][pi] = 0.0f;

    const float* srcs[3];
    srcs[0] = x    + (size_t)b * BSTRIDE;
    srcs[1] = g_Y1 + (size_t)b * BSTRIDE;
    srcs[2] = g_Y2 + (size_t)b * BSTRIDE;

    for (int s = 0; s < 3; s++) {
        const float* src = srcs[s];
        for (int cc = 0; cc < CIN; cc += 16) {
            __syncthreads();   // protect smem from previous chunk's readers
            // load input chunk [16 c x 256 pos] as 1024 float4 (4 per thread)
            #pragma unroll
            for (int r = 0; r < 4; r++) {
                const int idx  = tid + 256*r;      // float4 index
                const int c    = idx >> 6;         // 0..15
                const int col4 = idx & 63;
                const int pos  = p0 + col4*4;
                float4 v = make_float4(0.f, 0.f, 0.f, 0.f);
                if (pos < NT)
                    v = *(const float4*)(src + (size_t)(cc + c)*NT + pos);
                ((float4*)s_in)[c*64 + col4] = v;
            }
            // load W chunk [16 c x 64 o] = 256 float4 (1 per thread)
            ((float4*)s_W)[tid] =
                ((const float4*)(g_Wt + s*CIN*COUT + cc*COUT))[tid];
            __syncthreads();

            #pragma unroll
            for (int c = 0; c < 16; c++) {
                const float4 w0 = *(const float4*)(s_W + c*COUT + o0);
                const float4 w1 = *(const float4*)(s_W + c*COUT + o0 + 4);
                const float4 i0 = *(const float4*)(s_in + c*256 + pl);
                const float4 i1 = *(const float4*)(s_in + c*256 + pl + 4);
                const float wv[8] = {w0.x, w0.y, w0.z, w0.w, w1.x, w1.y, w1.z, w1.w};
                const float pv[8] = {i0.x, i0.y, i0.z, i0.w, i1.x, i1.y, i1.z, i1.w};
                #pragma unroll
                for (int oi = 0; oi < 8; oi++)
                    #pragma unroll
                    for (int pi = 0; pi < 8; pi++)
                        acc[oi][pi] += wv[oi] * pv[pi];
            }
        }
    }

    // epilogue: add bias, store
    const int pos = p0 + pl;
    if (pos < NT) {
        float* outb = out + (size_t)b * BSTRIDE;
        #pragma unroll
        for (int oi = 0; oi < 8; oi++) {
            const float bv = bias[o0 + oi];
            float* po = outb + (size_t)(o0 + oi)*NT + pos;
            float4 r0, r1;
            r0.x = acc[oi][0] + bv; r0.y = acc[oi][1] + bv;
            r0.z = acc[oi][2] + bv; r0.w = acc[oi][3] + bv;
            r1.x = acc[oi][4] + bv; r1.y = acc[oi][5] + bv;
            r1.z = acc[oi][6] + bv; r1.w = acc[oi][7] + bv;
            *(float4*)(po)     = r0;
            *(float4*)(po + 4) = r1;
        }
    }
}

// ---------------------------------------------------------------------------
// Inputs (metadata order): x [B,CIN,N,T] f32, adj [N,N] f32, W [COUT,3*CIN] f32,
//                          b [COUT] f32, K (ignored; baked as 3)
// ---------------------------------------------------------------------------
extern "C" void kernel_launch(void* const* d_in, const int* in_sizes, int n_in,
                              void* d_out, int out_size)
{
    const float* x    = (const float*)d_in[0];
    const float* adj  = (const float*)d_in[1];
    const float* W    = (const float*)d_in[2];
    const float* bias = (const float*)d_in[3];
    float* out = (float*)d_out;

    const int node_smem = (176*NNODE + 2*NT) * sizeof(float);  // 206,720 B
    cudaFuncSetAttribute(k_node, cudaFuncAttributeMaxDynamicSharedMemorySize,
                         node_smem);

    k_prep<<<48, 256>>>(W);
    k_node<<<BATCH*CIN, 256, node_smem>>>(x, adj);
    dim3 cgrid((NT + 255) / 256, BATCH);   // (43, 32)
    k_chan<<<cgrid, 256>>>(x, bias, out);
}

// round 4
// speedup vs baseline: 1.0293x; 1.0293x over previous
#include <cuda_runtime.h>

#define NNODE 170
#define NPAD  192
#define TSEQ  64
#define CIN   64
#define COUT  64
#define BATCH 32
#define NT    (NNODE*TSEQ)          // 10880
#define BSTRIDE (CIN*NT)            // 696320 (also COUT*NT for out)

typedef unsigned long long u64;

// Scratch (allocation-free rule: __device__ globals)
__device__ float g_Y1[BATCH*CIN*NT];
__device__ float g_Y2[BATCH*CIN*NT];
__device__ float g_Wt[3*CIN*COUT];  // [k][c][o]

// ---- packed fp32x2 helpers (sm_100+) --------------------------------------
__device__ __forceinline__ u64 pack2(float a, float b) {
    u64 r;
    asm("mov.b64 %0, {%1, %2};" : "=l"(r) : "f"(a), "f"(b));
    return r;
}
__device__ __forceinline__ void unpack2(u64 v, float& a, float& b) {
    asm("mov.b64 {%0, %1}, %2;" : "=f"(a), "=f"(b) : "l"(v));
}
__device__ __forceinline__ void fma2(u64& d, u64 a, u64 b) {
    asm("fma.rn.f32x2 %0, %1, %2, %3;" : "=l"(d) : "l"(a), "l"(b), "l"(d));
}

// ---------------------------------------------------------------------------
// Prep: transpose W[o, c*3+k] -> g_Wt[k][c][o]
// ---------------------------------------------------------------------------
__global__ void k_prep(const float* __restrict__ W)
{
    int i = blockIdx.x * 256 + threadIdx.x;
    if (i < 3*CIN*COUT) {
        int s = i / (CIN*COUT);
        int r = i % (CIN*COUT);
        int c = r / COUT;
        int o = r % COUT;
        g_Wt[i] = W[o*(3*CIN) + c*3 + s];
    }
}

// ---------------------------------------------------------------------------
// Node stage: per (b,c): Y1 = adj @ X,  Y2 = 2*adj @ Y1 - X
// Thread tile: 8 t (packed pairs) x 6 q-rows.  adj padded to 192 rows.
// smem: 192*170 + 2*10880 floats = 217,600 B (1 CTA/SM)
// ---------------------------------------------------------------------------
__global__ __launch_bounds__(256, 1) void k_node(const float* __restrict__ x,
                                                 const float* __restrict__ adj)
{
    extern __shared__ float sm[];
    float* s_adj = sm;                 // NPAD*170
    float* s_X   = sm + NPAD*NNODE;    // NT
    float* s_Y1  = s_X + NT;           // NT

    const int tid = threadIdx.x;
    const int bc  = blockIdx.x;
    const float* Xg = x + (size_t)bc * NT;
    float* Y1g = g_Y1 + (size_t)bc * NT;
    float* Y2g = g_Y2 + (size_t)bc * NT;

    for (int i = tid; i < NNODE*NNODE; i += 256) s_adj[i] = adj[i];
    for (int i = NNODE*NNODE + tid; i < NPAD*NNODE; i += 256) s_adj[i] = 0.0f;
    {
        const float4* Xg4 = (const float4*)Xg;
        float4* sX4 = (float4*)s_X;
        for (int i = tid; i < NT/4; i += 256) sX4[i] = Xg4[i];
    }
    __syncthreads();

    const int tx = tid & 7;           // t-pair group: t = tx*8 .. tx*8+7
    const int ty = tid >> 3;          // 0..31; q = ty + 32*j, j<6

    u64 acc[6][4];

    // ======== GEMM 1: Y1 = adj @ X ========
    #pragma unroll
    for (int j = 0; j < 6; j++)
        #pragma unroll
        for (int p = 0; p < 4; p++) acc[j][p] = 0ull;

    for (int n = 0; n < NNODE; n += 2) {
        const u64* xp0 = (const u64*)(s_X + (n  )*TSEQ + tx*8);
        const u64* xp1 = (const u64*)(s_X + (n+1)*TSEQ + tx*8);
        u64 xa0 = xp0[0], xa1 = xp0[1], xa2 = xp0[2], xa3 = xp0[3];
        u64 xb0 = xp1[0], xb1 = xp1[1], xb2 = xp1[2], xb3 = xp1[3];
        #pragma unroll
        for (int j = 0; j < 6; j++) {
            const float2 a2 = *(const float2*)(s_adj + (ty + 32*j)*NNODE + n);
            const u64 apA = pack2(a2.x, a2.x);
            const u64 apB = pack2(a2.y, a2.y);
            fma2(acc[j][0], apA, xa0);  fma2(acc[j][1], apA, xa1);
            fma2(acc[j][2], apA, xa2);  fma2(acc[j][3], apA, xa3);
            fma2(acc[j][0], apB, xb0);  fma2(acc[j][1], apB, xb1);
            fma2(acc[j][2], apB, xb2);  fma2(acc[j][3], apB, xb3);
        }
    }
    #pragma unroll
    for (int j = 0; j < 6; j++) {
        const int q = ty + 32*j;
        if (q < NNODE) {
            u64* ps = (u64*)(s_Y1 + q*TSEQ + tx*8);
            u64* pg = (u64*)(Y1g  + q*TSEQ + tx*8);
            #pragma unroll
            for (int p = 0; p < 4; p++) { ps[p] = acc[j][p]; pg[p] = acc[j][p]; }
        }
    }
    __syncthreads();

    // ======== GEMM 2: Y2 = 2*adj @ Y1 - X ========
    #pragma unroll
    for (int j = 0; j < 6; j++)
        #pragma unroll
        for (int p = 0; p < 4; p++) acc[j][p] = 0ull;

    for (int n = 0; n < NNODE; n += 2) {
        const u64* yp0 = (const u64*)(s_Y1 + (n  )*TSEQ + tx*8);
        const u64* yp1 = (const u64*)(s_Y1 + (n+1)*TSEQ + tx*8);
        u64 ya0 = yp0[0], ya1 = yp0[1], ya2 = yp0[2], ya3 = yp0[3];
        u64 yb0 = yp1[0], yb1 = yp1[1], yb2 = yp1[2], yb3 = yp1[3];
        #pragma unroll
        for (int j = 0; j < 6; j++) {
            const float2 a2 = *(const float2*)(s_adj + (ty + 32*j)*NNODE + n);
            const u64 apA = pack2(a2.x, a2.x);
            const u64 apB = pack2(a2.y, a2.y);
            fma2(acc[j][0], apA, ya0);  fma2(acc[j][1], apA, ya1);
            fma2(acc[j][2], apA, ya2);  fma2(acc[j][3], apA, ya3);
            fma2(acc[j][0], apB, yb0);  fma2(acc[j][1], apB, yb1);
            fma2(acc[j][2], apB, yb2);  fma2(acc[j][3], apB, yb3);
        }
    }
    #pragma unroll
    for (int j = 0; j < 6; j++) {
        const int q = ty + 32*j;
        if (q < NNODE) {
            const float* xr = s_X + q*TSEQ + tx*8;
            float* pg = Y2g + q*TSEQ + tx*8;
            #pragma unroll
            for (int p = 0; p < 4; p++) {
                float lo, hi;
                unpack2(acc[j][p], lo, hi);
                float2 r;
                r.x = 2.f*lo - xr[p*2];
                r.y = 2.f*hi - xr[p*2 + 1];
                *(float2*)(pg + p*2) = r;
            }
        }
    }
}

// ---------------------------------------------------------------------------
// Channel stage: out[b,o,pos] = bias[o] + sum_{s,c} Wt[s][c][o]*src_s[b,c,pos]
// Thread = 8 o x 4 pos-pairs (f32x2 accumulators along contiguous pos).
// ---------------------------------------------------------------------------
__global__ __launch_bounds__(256, 2) void k_chan(const float* __restrict__ x,
                                                 const float* __restrict__ bias,
                                                 float* __restrict__ out)
{
    __shared__ float s_in[16*256];   // [c][pos]
    __shared__ float s_W[16*COUT];   // [c][o]

    const int tid = threadIdx.x;
    const int b   = blockIdx.y;
    const int p0  = blockIdx.x * 256;
    const int og  = tid >> 5;        // 0..7
    const int pg  = tid & 31;        // 0..31
    const int o0  = og * 8;
    const int pl  = pg * 8;

    u64 acc[8][4];
    #pragma unroll
    for (int oi = 0; oi < 8; oi++)
        #pragma unroll
        for (int p = 0; p < 4; p++) acc[oi][p] = 0ull;

    const float* srcs[3];
    srcs[0] = x    + (size_t)b * BSTRIDE;
    srcs[1] = g_Y1 + (size_t)b * BSTRIDE;
    srcs[2] = g_Y2 + (size_t)b * BSTRIDE;

    for (int s = 0; s < 3; s++) {
        const float* src = srcs[s];
        for (int cc = 0; cc < CIN; cc += 16) {
            __syncthreads();
            #pragma unroll
            for (int r = 0; r < 4; r++) {
                const int idx  = tid + 256*r;
                const int c    = idx >> 6;
                const int col4 = idx & 63;
                const int pos  = p0 + col4*4;
                float4 v = make_float4(0.f, 0.f, 0.f, 0.f);
                if (pos < NT)
                    v = *(const float4*)(src + (size_t)(cc + c)*NT + pos);
                ((float4*)s_in)[c*64 + col4] = v;
            }
            ((float4*)s_W)[tid] =
                ((const float4*)(g_Wt + s*CIN*COUT + cc*COUT))[tid];
            __syncthreads();

            #pragma unroll
            for (int c = 0; c < 16; c++) {
                const float4 w0 = *(const float4*)(s_W + c*COUT + o0);
                const float4 w1 = *(const float4*)(s_W + c*COUT + o0 + 4);
                const u64* ip = (const u64*)(s_in + c*256 + pl);
                const u64 i0 = ip[0], i1 = ip[1], i2 = ip[2], i3 = ip[3];
                const u64 wp[8] = {
                    pack2(w0.x, w0.x), pack2(w0.y, w0.y),
                    pack2(w0.z, w0.z), pack2(w0.w, w0.w),
                    pack2(w1.x, w1.x), pack2(w1.y, w1.y),
                    pack2(w1.z, w1.z), pack2(w1.w, w1.w) };
                #pragma unroll
                for (int oi = 0; oi < 8; oi++) {
                    fma2(acc[oi][0], wp[oi], i0);
                    fma2(acc[oi][1], wp[oi], i1);
                    fma2(acc[oi][2], wp[oi], i2);
                    fma2(acc[oi][3], wp[oi], i3);
                }
            }
        }
    }

    // epilogue: add bias, store
    const int pos = p0 + pl;
    if (pos < NT) {
        float* outb = out + (size_t)b * BSTRIDE;
        #pragma unroll
        for (int oi = 0; oi < 8; oi++) {
            const float bv = bias[o0 + oi];
            float* po = outb + (size_t)(o0 + oi)*NT + pos;
            float r[8];
            #pragma unroll
            for (int p = 0; p < 4; p++) {
                float lo, hi;
                unpack2(acc[oi][p], lo, hi);
                r[p*2]   = lo + bv;
                r[p*2+1] = hi + bv;
            }
            *(float4*)(po)     = make_float4(r[0], r[1], r[2], r[3]);
            *(float4*)(po + 4) = make_float4(r[4], r[5], r[6], r[7]);
        }
    }
}

// ---------------------------------------------------------------------------
extern "C" void kernel_launch(void* const* d_in, const int* in_sizes, int n_in,
                              void* d_out, int out_size)
{
    const float* x    = (const float*)d_in[0];
    const float* adj  = (const float*)d_in[1];
    const float* W    = (const float*)d_in[2];
    const float* bias = (const float*)d_in[3];
    float* out = (float*)d_out;

    const int node_smem = (NPAD*NNODE + 2*NT) * sizeof(float);  // 217,600 B
    cudaFuncSetAttribute(k_node, cudaFuncAttributeMaxDynamicSharedMemorySize,
                         node_smem);

    k_prep<<<48, 256>>>(W);
    k_node<<<BATCH*CIN, 256, node_smem>>>(x, adj);
    dim3 cgrid((NT + 255) / 256, BATCH);   // (43, 32)
    k_chan<<<cgrid, 256>>>(x, bias, out);
}

// round 8
// speedup vs baseline: 1.5645x; 1.5199x over previous
#include <cuda_runtime.h>
#include <cuda_bf16.h>
#include <cstdint>

#define NNODE 170
#define MPAD  176          // node dim padded to 11 m-tiles of 16
#define SA    184          // adj smem row stride (elems)
#define SB    72           // X/Y1 smem row stride (elems)
#define TSEQ  64
#define CIN   64
#define COUT  64
#define BATCH 32
#define NT    (NNODE*TSEQ)          // 10880
#define BSTRIDE (CIN*NT)

typedef unsigned long long u64;

// ---------------- device scratch (no allocs allowed) -----------------------
__device__ float g_Y1[BATCH*CIN*NT];
__device__ float g_Y2[BATCH*CIN*NT];
__device__ float g_Wt[3*CIN*COUT];                      // [k][c][o]
__device__ __align__(16) __nv_bfloat16 g_adjh[MPAD*SA]; // padded [176][184]
__device__ __align__(16) __nv_bfloat16 g_adjl[MPAD*SA];

// ---------------- smem map (bytes) -----------------------------------------
#define AH_OFF 0                        // 176*184*2 = 64768
#define AL_OFF 64768
#define BH_OFF 129536                   // 176*72*2  = 25344
#define BL_OFF 154880
#define NODE_SMEM 180224

// ---------------- helpers ---------------------------------------------------
__device__ __forceinline__ uint32_t smem_u32(const void* p) {
    uint32_t a;
    asm("{ .reg .u64 t; cvta.to.shared.u64 t, %1; cvt.u32.u64 %0, t; }"
        : "=r"(a) : "l"(p));
    return a;
}

#define LDSM_X4(r, addr) \
    asm volatile("ldmatrix.sync.aligned.m8n8.x4.shared.b16 {%0,%1,%2,%3}, [%4];" \
        : "=r"((r)[0]), "=r"((r)[1]), "=r"((r)[2]), "=r"((r)[3]) : "r"(addr))
#define LDSM_X4T(r, addr) \
    asm volatile("ldmatrix.sync.aligned.m8n8.x4.trans.shared.b16 {%0,%1,%2,%3}, [%4];" \
        : "=r"((r)[0]), "=r"((r)[1]), "=r"((r)[2]), "=r"((r)[3]) : "r"(addr))

#define MMA_BF16(d, a, b0, b1) \
    asm volatile("mma.sync.aligned.m16n8k16.row.col.f32.bf16.bf16.f32 " \
        "{%0,%1,%2,%3}, {%4,%5,%6,%7}, {%8,%9}, {%0,%1,%2,%3};" \
        : "+f"((d)[0]), "+f"((d)[1]), "+f"((d)[2]), "+f"((d)[3]) \
        : "r"((a)[0]), "r"((a)[1]), "r"((a)[2]), "r"((a)[3]), "r"(b0), "r"(b1))

__device__ __forceinline__ void split_bf16(float v, __nv_bfloat16& h, __nv_bfloat16& l) {
    h = __float2bfloat16(v);
    l = __float2bfloat16(v - __bfloat162float(h));
}

// packed fp32x2 helpers (k_chan)
__device__ __forceinline__ u64 pack2(float a, float b) {
    u64 r; asm("mov.b64 %0, {%1, %2};" : "=l"(r) : "f"(a), "f"(b)); return r;
}
__device__ __forceinline__ void unpack2(u64 v, float& a, float& b) {
    asm("mov.b64 {%0, %1}, %2;" : "=f"(a), "=f"(b) : "l"(v));
}
__device__ __forceinline__ void fma2(u64& d, u64 a, u64 b) {
    asm("fma.rn.f32x2 %0, %1, %2, %3;" : "=l"(d) : "l"(a), "l"(b), "l"(d));
}

// ---------------------------------------------------------------------------
// Prep kernels
// ---------------------------------------------------------------------------
__global__ void k_prep(const float* __restrict__ W)
{
    int i = blockIdx.x * 256 + threadIdx.x;
    if (i < 3*CIN*COUT) {
        int s = i / (CIN*COUT);
        int r = i % (CIN*COUT);
        int c = r / COUT;
        int o = r % COUT;
        g_Wt[i] = W[o*(3*CIN) + c*3 + s];
    }
}

__global__ void k_prep_adj(const float* __restrict__ adj)
{
    int i = blockIdx.x * 256 + threadIdx.x;
    if (i >= MPAD*SA) return;
    int q = i / SA, k = i % SA;
    float a = (q < NNODE && k < NNODE) ? adj[q*NNODE + k] : 0.0f;
    __nv_bfloat16 h, l;
    split_bf16(a, h, l);
    g_adjh[i] = h;
    g_adjl[i] = l;
}

// ---------------------------------------------------------------------------
// One split-bf16 GEMM pass: acc[q,t] = adj(hi/lo) @ B(hi/lo)
// warp w owns m-tiles {w, w+8}; acc[half][nt][4]
// ---------------------------------------------------------------------------
__device__ __forceinline__ void run_gemm(uint32_t aH, uint32_t aL,
                                         uint32_t bH, uint32_t bL,
                                         int w, int lane, float acc[2][8][4])
{
    #pragma unroll
    for (int h = 0; h < 2; h++)
        #pragma unroll
        for (int n = 0; n < 8; n++)
            #pragma unroll
            for (int p = 0; p < 4; p++) acc[h][n][p] = 0.0f;

    const int brow_l = lane & 15;
    const int bcol_l = (lane >> 4) * 8;

    for (int k0 = 0; k0 < MPAD; k0 += 16) {
        uint32_t bh[4][4], bl[4][4];
        const uint32_t bbase = (uint32_t)((k0 + brow_l) * SB + bcol_l) * 2;
        #pragma unroll
        for (int p = 0; p < 4; p++) {
            LDSM_X4T(bh[p], bH + bbase + p*32);   // p*16 cols * 2B
            LDSM_X4T(bl[p], bL + bbase + p*32);
        }
        #pragma unroll
        for (int half = 0; half < 2; half++) {
            const int mt = w + half*8;
            if (mt < 11) {
                uint32_t ah[4], al[4];
                const uint32_t abase =
                    (uint32_t)((mt*16 + brow_l) * SA + k0 + bcol_l) * 2;
                LDSM_X4(ah, aH + abase);
                LDSM_X4(al, aL + abase);
                #pragma unroll
                for (int p = 0; p < 4; p++)
                    #pragma unroll
                    for (int s = 0; s < 2; s++) {
                        float* d = acc[half][p*2 + s];
                        MMA_BF16(d, ah, bh[p][s*2], bh[p][s*2+1]);
                        MMA_BF16(d, ah, bl[p][s*2], bl[p][s*2+1]);
                        MMA_BF16(d, al, bh[p][s*2], bh[p][s*2+1]);
                    }
            }
        }
    }
}

// ---------------------------------------------------------------------------
// Node stage via mma.sync: per CTA = one (b,c)
//   Y1 = adj @ X ;  Y2 = 2*adj @ Y1 - X
// ---------------------------------------------------------------------------
__global__ __launch_bounds__(256, 1) void k_node_hmma(const float* __restrict__ x)
{
    extern __shared__ char smem[];
    const uint32_t sbase = smem_u32(smem);
    const uint32_t aH = sbase + AH_OFF, aL = sbase + AL_OFF;
    const uint32_t bHo = sbase + BH_OFF, bLo = sbase + BL_OFF;
    __nv_bfloat16* sBH = (__nv_bfloat16*)(smem + BH_OFF);
    __nv_bfloat16* sBL = (__nv_bfloat16*)(smem + BL_OFF);

    const int tid  = threadIdx.x;
    const int w    = tid >> 5;
    const int lane = tid & 31;
    const int bc   = blockIdx.x;
    const float* Xg = x + (size_t)bc * NT;
    float* Y1g = g_Y1 + (size_t)bc * NT;
    float* Y2g = g_Y2 + (size_t)bc * NT;

    // ---- stage adj hi/lo (L2-resident padded images) ----
    {
        const float4* gh = (const float4*)g_adjh;
        const float4* gl = (const float4*)g_adjl;
        float4* dh = (float4*)(smem + AH_OFF);
        float4* dl = (float4*)(smem + AL_OFF);
        for (int i = tid; i < (MPAD*SA*2)/16; i += 256) { dh[i] = gh[i]; dl[i] = gl[i]; }
    }
    // ---- stage X hi/lo (natural [node][t] layout) ----
    for (int i = tid; i < NNODE*TSEQ; i += 256) {
        const int r = i >> 6, t = i & 63;
        __nv_bfloat16 h, l;
        split_bf16(Xg[i], h, l);
        sBH[r*SB + t] = h;
        sBL[r*SB + t] = l;
    }
    for (int i = tid; i < (MPAD - NNODE)*SB; i += 256) {   // zero pad rows
        const int idx = NNODE*SB + i;
        sBH[idx] = __float2bfloat16(0.f);
        sBL[idx] = __float2bfloat16(0.f);
    }
    __syncthreads();

    float acc[2][8][4];
    const int g  = lane >> 2;
    const int c2 = (lane & 3) * 2;

    // ======== GEMM 1: Y1 = adj @ X ========
    run_gemm(aH, aL, bHo, bLo, w, lane, acc);
    __syncthreads();   // all warps done reading B before we overwrite it

    #pragma unroll
    for (int half = 0; half < 2; half++) {
        const int mt = w + half*8;
        if (mt < 11) {
            #pragma unroll
            for (int nt = 0; nt < 8; nt++) {
                const int t = nt*8 + c2;
                #pragma unroll
                for (int rr = 0; rr < 2; rr++) {
                    const int q = mt*16 + g + rr*8;
                    const float v0 = acc[half][nt][rr*2];
                    const float v1 = acc[half][nt][rr*2+1];
                    if (q < NNODE) {
                        float2 o; o.x = v0; o.y = v1;
                        *(float2*)(Y1g + q*TSEQ + t) = o;
                    }
                    __nv_bfloat162 h2, l2;
                    split_bf16(v0, h2.x, l2.x);
                    split_bf16(v1, h2.y, l2.y);
                    *(__nv_bfloat162*)(sBH + q*SB + t) = h2;   // q<176: rows >=170 write zeros
                    *(__nv_bfloat162*)(sBL + q*SB + t) = l2;
                }
            }
        }
    }
    __syncthreads();

    // ======== GEMM 2: Y2 = 2*adj @ Y1 - X ========
    run_gemm(aH, aL, bHo, bLo, w, lane, acc);

    #pragma unroll
    for (int half = 0; half < 2; half++) {
        const int mt = w + half*8;
        if (mt < 11) {
            #pragma unroll
            for (int nt = 0; nt < 8; nt++) {
                const int t = nt*8 + c2;
                #pragma unroll
                for (int rr = 0; rr < 2; rr++) {
                    const int q = mt*16 + g + rr*8;
                    if (q < NNODE) {
                        const float2 xv = *(const float2*)(Xg + q*TSEQ + t);
                        float2 o;
                        o.x = 2.f*acc[half][nt][rr*2]   - xv.x;
                        o.y = 2.f*acc[half][nt][rr*2+1] - xv.y;
                        *(float2*)(Y2g + q*TSEQ + t) = o;
                    }
                }
            }
        }
    }
}

// ---------------------------------------------------------------------------
// Channel stage (unchanged): out = bias + Wt . [X;Y1;Y2]
// ---------------------------------------------------------------------------
__global__ __launch_bounds__(256, 2) void k_chan(const float* __restrict__ x,
                                                 const float* __restrict__ bias,
                                                 float* __restrict__ out)
{
    __shared__ float s_in[16*256];
    __shared__ float s_W[16*COUT];

    const int tid = threadIdx.x;
    const int b   = blockIdx.y;
    const int p0  = blockIdx.x * 256;
    const int og  = tid >> 5;
    const int pg  = tid & 31;
    const int o0  = og * 8;
    const int pl  = pg * 8;

    u64 acc[8][4];
    #pragma unroll
    for (int oi = 0; oi < 8; oi++)
        #pragma unroll
        for (int p = 0; p < 4; p++) acc[oi][p] = 0ull;

    const float* srcs[3];
    srcs[0] = x    + (size_t)b * BSTRIDE;
    srcs[1] = g_Y1 + (size_t)b * BSTRIDE;
    srcs[2] = g_Y2 + (size_t)b * BSTRIDE;

    for (int s = 0; s < 3; s++) {
        const float* src = srcs[s];
        for (int cc = 0; cc < CIN; cc += 16) {
            __syncthreads();
            #pragma unroll
            for (int rr = 0; rr < 4; rr++) {
                const int idx  = tid + 256*rr;
                const int c    = idx >> 6;
                const int col4 = idx & 63;
                const int pos  = p0 + col4*4;
                float4 v = make_float4(0.f, 0.f, 0.f, 0.f);
                if (pos < NT)
                    v = *(const float4*)(src + (size_t)(cc + c)*NT + pos);
                ((float4*)s_in)[c*64 + col4] = v;
            }
            ((float4*)s_W)[tid] =
                ((const float4*)(g_Wt + s*CIN*COUT + cc*COUT))[tid];
            __syncthreads();

            #pragma unroll
            for (int c = 0; c < 16; c++) {
                const float4 w0 = *(const float4*)(s_W + c*COUT + o0);
                const float4 w1 = *(const float4*)(s_W + c*COUT + o0 + 4);
                const u64* ip = (const u64*)(s_in + c*256 + pl);
                const u64 i0 = ip[0], i1 = ip[1], i2 = ip[2], i3 = ip[3];
                const u64 wp[8] = {
                    pack2(w0.x, w0.x), pack2(w0.y, w0.y),
                    pack2(w0.z, w0.z), pack2(w0.w, w0.w),
                    pack2(w1.x, w1.x), pack2(w1.y, w1.y),
                    pack2(w1.z, w1.z), pack2(w1.w, w1.w) };
                #pragma unroll
                for (int oi = 0; oi < 8; oi++) {
                    fma2(acc[oi][0], wp[oi], i0);
                    fma2(acc[oi][1], wp[oi], i1);
                    fma2(acc[oi][2], wp[oi], i2);
                    fma2(acc[oi][3], wp[oi], i3);
                }
            }
        }
    }

    const int pos = p0 + pl;
    if (pos < NT) {
        float* outb = out + (size_t)b * BSTRIDE;
        #pragma unroll
        for (int oi = 0; oi < 8; oi++) {
            const float bv = bias[o0 + oi];
            float* po = outb + (size_t)(o0 + oi)*NT + pos;
            float rr[8];
            #pragma unroll
            for (int p = 0; p < 4; p++) {
                float lo, hi;
                unpack2(acc[oi][p], lo, hi);
                rr[p*2]   = lo + bv;
                rr[p*2+1] = hi + bv;
            }
            *(float4*)(po)     = make_float4(rr[0], rr[1], rr[2], rr[3]);
            *(float4*)(po + 4) = make_float4(rr[4], rr[5], rr[6], rr[7]);
        }
    }
}

// ---------------------------------------------------------------------------
extern "C" void kernel_launch(void* const* d_in, const int* in_sizes, int n_in,
                              void* d_out, int out_size)
{
    const float* x    = (const float*)d_in[0];
    const float* adj  = (const float*)d_in[1];
    const float* W    = (const float*)d_in[2];
    const float* bias = (const float*)d_in[3];
    float* out = (float*)d_out;

    cudaFuncSetAttribute(k_node_hmma, cudaFuncAttributeMaxDynamicSharedMemorySize,
                         NODE_SMEM);

    k_prep<<<48, 256>>>(W);
    k_prep_adj<<<(MPAD*SA + 255)/256, 256>>>(adj);
    k_node_hmma<<<BATCH*CIN, 256, NODE_SMEM>>>(x);
    dim3 cgrid((NT + 255) / 256, BATCH);
    k_chan<<<cgrid, 256>>>(x, bias, out);
}

// round 9
// speedup vs baseline: 1.8105x; 1.1572x over previous
#include <cuda_runtime.h>
#include <cuda_bf16.h>
#include <cstdint>

#define NNODE 170
#define MPAD  176          // node dim padded to 11 m-tiles of 16
#define SA    184          // adj smem row stride (elems)
#define SB    72           // X/Y1 smem row stride (elems)
#define TSEQ  64
#define CIN   64
#define COUT  64
#define BATCH 32
#define NT    (NNODE*TSEQ)          // 10880 = 85 * 128
#define BSTRIDE (CIN*NT)

#define KCH   192          // channel-stage K = 3*CIN
#define SW    200          // W image row stride (elems)
#define SC    136          // chan B tile row stride (elems)
#define PTILE 128          // pos per chan CTA

typedef unsigned long long u64;

// ---------------- device scratch (no allocs allowed) -----------------------
__device__ float g_Y1[BATCH*CIN*NT];
__device__ float g_Y2[BATCH*CIN*NT];
__device__ __align__(16) __nv_bfloat16 g_adjh[MPAD*SA]; // padded [176][184]
__device__ __align__(16) __nv_bfloat16 g_adjl[MPAD*SA];
__device__ __align__(16) __nv_bfloat16 g_Wh[COUT*SW];   // [o][k=s*64+c] hi
__device__ __align__(16) __nv_bfloat16 g_Wl[COUT*SW];   // lo

// ---------------- node smem map (bytes) -------------------------------------
#define AH_OFF 0                        // 176*184*2 = 64768
#define AL_OFF 64768
#define BH_OFF 129536                   // 176*72*2  = 25344
#define BL_OFF 154880
#define NODE_SMEM 180224

// ---------------- chan smem map (bytes) -------------------------------------
#define WH_OFF 0                        // 64*200*2 = 25600
#define WL_OFF 25600
#define CBH_OFF 51200                   // 192*136*2 = 52224
#define CBL_OFF 103424
#define CHAN_SMEM 155648

// ---------------- helpers ---------------------------------------------------
__device__ __forceinline__ uint32_t smem_u32(const void* p) {
    uint32_t a;
    asm("{ .reg .u64 t; cvta.to.shared.u64 t, %1; cvt.u32.u64 %0, t; }"
        : "=r"(a) : "l"(p));
    return a;
}

#define LDSM_X4(r, addr) \
    asm volatile("ldmatrix.sync.aligned.m8n8.x4.shared.b16 {%0,%1,%2,%3}, [%4];" \
        : "=r"((r)[0]), "=r"((r)[1]), "=r"((r)[2]), "=r"((r)[3]) : "r"(addr))
#define LDSM_X4T(r, addr) \
    asm volatile("ldmatrix.sync.aligned.m8n8.x4.trans.shared.b16 {%0,%1,%2,%3}, [%4];" \
        : "=r"((r)[0]), "=r"((r)[1]), "=r"((r)[2]), "=r"((r)[3]) : "r"(addr))

#define MMA_BF16(d, a, b0, b1) \
    asm volatile("mma.sync.aligned.m16n8k16.row.col.f32.bf16.bf16.f32 " \
        "{%0,%1,%2,%3}, {%4,%5,%6,%7}, {%8,%9}, {%0,%1,%2,%3};" \
        : "+f"((d)[0]), "+f"((d)[1]), "+f"((d)[2]), "+f"((d)[3]) \
        : "r"((a)[0]), "r"((a)[1]), "r"((a)[2]), "r"((a)[3]), "r"(b0), "r"(b1))

__device__ __forceinline__ void split_bf16(float v, __nv_bfloat16& h, __nv_bfloat16& l) {
    h = __float2bfloat16(v);
    l = __float2bfloat16(v - __bfloat162float(h));
}

// ---------------------------------------------------------------------------
// Prep kernels
// ---------------------------------------------------------------------------
__global__ void k_prep_w(const float* __restrict__ W)
{
    int i = blockIdx.x * 256 + threadIdx.x;     // over 64*SW
    if (i >= COUT*SW) return;
    int o = i / SW, k = i % SW;
    float v = 0.0f;
    if (k < KCH) {
        int s = k >> 6, c = k & 63;
        v = W[o*KCH + c*3 + s];
    }
    __nv_bfloat16 h, l;
    split_bf16(v, h, l);
    g_Wh[i] = h;
    g_Wl[i] = l;
}

__global__ void k_prep_adj(const float* __restrict__ adj)
{
    int i = blockIdx.x * 256 + threadIdx.x;
    if (i >= MPAD*SA) return;
    int q = i / SA, k = i % SA;
    float a = (q < NNODE && k < NNODE) ? adj[q*NNODE + k] : 0.0f;
    __nv_bfloat16 h, l;
    split_bf16(a, h, l);
    g_adjh[i] = h;
    g_adjl[i] = l;
}

// ---------------------------------------------------------------------------
// One split-bf16 GEMM pass (node): acc[q,t] = adj(hi/lo) @ B(hi/lo)
// ---------------------------------------------------------------------------
__device__ __forceinline__ void run_gemm(uint32_t aH, uint32_t aL,
                                         uint32_t bH, uint32_t bL,
                                         int w, int lane, float acc[2][8][4])
{
    #pragma unroll
    for (int h = 0; h < 2; h++)
        #pragma unroll
        for (int n = 0; n < 8; n++)
            #pragma unroll
            for (int p = 0; p < 4; p++) acc[h][n][p] = 0.0f;

    const int brow_l = lane & 15;
    const int bcol_l = (lane >> 4) * 8;

    for (int k0 = 0; k0 < MPAD; k0 += 16) {
        uint32_t bh[4][4], bl[4][4];
        const uint32_t bbase = (uint32_t)((k0 + brow_l) * SB + bcol_l) * 2;
        #pragma unroll
        for (int p = 0; p < 4; p++) {
            LDSM_X4T(bh[p], bH + bbase + p*32);
            LDSM_X4T(bl[p], bL + bbase + p*32);
        }
        #pragma unroll
        for (int half = 0; half < 2; half++) {
            const int mt = w + half*8;
            if (mt < 11) {
                uint32_t ah[4], al[4];
                const uint32_t abase =
                    (uint32_t)((mt*16 + brow_l) * SA + k0 + bcol_l) * 2;
                LDSM_X4(ah, aH + abase);
                LDSM_X4(al, aL + abase);
                #pragma unroll
                for (int p = 0; p < 4; p++)
                    #pragma unroll
                    for (int s = 0; s < 2; s++) {
                        float* d = acc[half][p*2 + s];
                        MMA_BF16(d, ah, bh[p][s*2], bh[p][s*2+1]);
                        MMA_BF16(d, ah, bl[p][s*2], bl[p][s*2+1]);
                        MMA_BF16(d, al, bh[p][s*2], bh[p][s*2+1]);
                    }
            }
        }
    }
}

// ---------------------------------------------------------------------------
// Node stage (unchanged from R6): per CTA = one (b,c)
// ---------------------------------------------------------------------------
__global__ __launch_bounds__(256, 1) void k_node_hmma(const float* __restrict__ x)
{
    extern __shared__ char smem[];
    const uint32_t sbase = smem_u32(smem);
    const uint32_t aH = sbase + AH_OFF, aL = sbase + AL_OFF;
    const uint32_t bHo = sbase + BH_OFF, bLo = sbase + BL_OFF;
    __nv_bfloat16* sBH = (__nv_bfloat16*)(smem + BH_OFF);
    __nv_bfloat16* sBL = (__nv_bfloat16*)(smem + BL_OFF);

    const int tid  = threadIdx.x;
    const int w    = tid >> 5;
    const int lane = tid & 31;
    const int bc   = blockIdx.x;
    const float* Xg = x + (size_t)bc * NT;
    float* Y1g = g_Y1 + (size_t)bc * NT;
    float* Y2g = g_Y2 + (size_t)bc * NT;

    {
        const float4* gh = (const float4*)g_adjh;
        const float4* gl = (const float4*)g_adjl;
        float4* dh = (float4*)(smem + AH_OFF);
        float4* dl = (float4*)(smem + AL_OFF);
        for (int i = tid; i < (MPAD*SA*2)/16; i += 256) { dh[i] = gh[i]; dl[i] = gl[i]; }
    }
    for (int i = tid; i < NNODE*TSEQ; i += 256) {
        const int r = i >> 6, t = i & 63;
        __nv_bfloat16 h, l;
        split_bf16(Xg[i], h, l);
        sBH[r*SB + t] = h;
        sBL[r*SB + t] = l;
    }
    for (int i = tid; i < (MPAD - NNODE)*SB; i += 256) {
        const int idx = NNODE*SB + i;
        sBH[idx] = __float2bfloat16(0.f);
        sBL[idx] = __float2bfloat16(0.f);
    }
    __syncthreads();

    float acc[2][8][4];
    const int g  = lane >> 2;
    const int c2 = (lane & 3) * 2;

    run_gemm(aH, aL, bHo, bLo, w, lane, acc);
    __syncthreads();

    #pragma unroll
    for (int half = 0; half < 2; half++) {
        const int mt = w + half*8;
        if (mt < 11) {
            #pragma unroll
            for (int nt = 0; nt < 8; nt++) {
                const int t = nt*8 + c2;
                #pragma unroll
                for (int rr = 0; rr < 2; rr++) {
                    const int q = mt*16 + g + rr*8;
                    const float v0 = acc[half][nt][rr*2];
                    const float v1 = acc[half][nt][rr*2+1];
                    if (q < NNODE) {
                        float2 o; o.x = v0; o.y = v1;
                        *(float2*)(Y1g + q*TSEQ + t) = o;
                    }
                    __nv_bfloat162 h2, l2;
                    split_bf16(v0, h2.x, l2.x);
                    split_bf16(v1, h2.y, l2.y);
                    *(__nv_bfloat162*)(sBH + q*SB + t) = h2;
                    *(__nv_bfloat162*)(sBL + q*SB + t) = l2;
                }
            }
        }
    }
    __syncthreads();

    run_gemm(aH, aL, bHo, bLo, w, lane, acc);

    #pragma unroll
    for (int half = 0; half < 2; half++) {
        const int mt = w + half*8;
        if (mt < 11) {
            #pragma unroll
            for (int nt = 0; nt < 8; nt++) {
                const int t = nt*8 + c2;
                #pragma unroll
                for (int rr = 0; rr < 2; rr++) {
                    const int q = mt*16 + g + rr*8;
                    if (q < NNODE) {
                        const float2 xv = *(const float2*)(Xg + q*TSEQ + t);
                        float2 o;
                        o.x = 2.f*acc[half][nt][rr*2]   - xv.x;
                        o.y = 2.f*acc[half][nt][rr*2+1] - xv.y;
                        *(float2*)(Y2g + q*TSEQ + t) = o;
                    }
                }
            }
        }
    }
}

// ---------------------------------------------------------------------------
// Channel stage via HMMA: out[b, o, pos] = bias[o] + Wcat[o, :] @ S[:, pos]
// CTA = 128-pos tile of one batch. K=192 (s*64+c). 8 warps = 2(m) x 4(n).
// ---------------------------------------------------------------------------
__global__ __launch_bounds__(256, 1) void k_chan_hmma(const float* __restrict__ x,
                                                      const float* __restrict__ bias,
                                                      float* __restrict__ out)
{
    extern __shared__ char smem[];
    const uint32_t sbase = smem_u32(smem);
    const uint32_t wH = sbase + WH_OFF, wL = sbase + WL_OFF;
    const uint32_t cH = sbase + CBH_OFF, cL = sbase + CBL_OFF;
    __nv_bfloat16* sBH = (__nv_bfloat16*)(smem + CBH_OFF);
    __nv_bfloat16* sBL = (__nv_bfloat16*)(smem + CBL_OFF);

    const int tid  = threadIdx.x;
    const int w    = tid >> 5;
    const int lane = tid & 31;
    const int wm   = w & 1;          // m half: o 0-31 / 32-63
    const int wn   = w >> 1;         // n quarter: 32 pos each
    const int b    = blockIdx.y;
    const int p0   = blockIdx.x * PTILE;

    const float* srcs[3];
    srcs[0] = x    + (size_t)b * BSTRIDE;
    srcs[1] = g_Y1 + (size_t)b * BSTRIDE;
    srcs[2] = g_Y2 + (size_t)b * BSTRIDE;

    // ---- stage W hi/lo images (L2-resident) ----
    {
        const float4* gh = (const float4*)g_Wh;
        const float4* gl = (const float4*)g_Wl;
        float4* dh = (float4*)(smem + WH_OFF);
        float4* dl = (float4*)(smem + WL_OFF);
        for (int i = tid; i < (COUT*SW*2)/16; i += 256) { dh[i] = gh[i]; dl[i] = gl[i]; }
    }
    // ---- stage B tile [192][128] f32 -> bf16 hi/lo ----
    for (int idx = tid; idx < KCH*(PTILE/4); idx += 256) {   // 6144 float4
        const int k  = idx >> 5;          // 0..191
        const int p4 = idx & 31;
        const float4 v = *(const float4*)(srcs[k >> 6] + (size_t)(k & 63)*NT + p0 + p4*4);
        __nv_bfloat16 h0,l0,h1,l1,h2,l2,h3,l3;
        split_bf16(v.x, h0, l0); split_bf16(v.y, h1, l1);
        split_bf16(v.z, h2, l2); split_bf16(v.w, h3, l3);
        __nv_bfloat162 hh[2] = { {h0,h1}, {h2,h3} };
        __nv_bfloat162 ll[2] = { {l0,l1}, {l2,l3} };
        *(uint2*)(sBH + k*SC + p4*4) = *(uint2*)hh;
        *(uint2*)(sBL + k*SC + p4*4) = *(uint2*)ll;
    }
    __syncthreads();

    // ---- GEMM: M=64, N=128, K=192, 3 split passes ----
    float acc[2][4][4];
    #pragma unroll
    for (int mi = 0; mi < 2; mi++)
        #pragma unroll
        for (int ni = 0; ni < 4; ni++)
            #pragma unroll
            for (int p = 0; p < 4; p++) acc[mi][ni][p] = 0.0f;

    const int brow_l = lane & 15;
    const int bcol_l = (lane >> 4) * 8;

    for (int k0 = 0; k0 < KCH; k0 += 16) {
        uint32_t bh[2][4], bl[2][4];
        #pragma unroll
        for (int gB = 0; gB < 2; gB++) {
            const uint32_t bb =
                (uint32_t)((k0 + brow_l)*SC + wn*32 + gB*16 + bcol_l) * 2;
            LDSM_X4T(bh[gB], cH + bb);
            LDSM_X4T(bl[gB], cL + bb);
        }
        #pragma unroll
        for (int mi = 0; mi < 2; mi++) {
            uint32_t ah[4], al[4];
            const uint32_t ab =
                (uint32_t)(((wm*2 + mi)*16 + brow_l)*SW + k0 + bcol_l) * 2;
            LDSM_X4(ah, wH + ab);
            LDSM_X4(al, wL + ab);
            #pragma unroll
            for (int gB = 0; gB < 2; gB++)
                #pragma unroll
                for (int s = 0; s < 2; s++) {
                    float* d = acc[mi][gB*2 + s];
                    MMA_BF16(d, ah, bh[gB][s*2], bh[gB][s*2+1]);
                    MMA_BF16(d, ah, bl[gB][s*2], bl[gB][s*2+1]);
                    MMA_BF16(d, al, bh[gB][s*2], bh[gB][s*2+1]);
                }
        }
    }

    // ---- epilogue: bias + store ----
    const int g  = lane >> 2;
    const int c2 = (lane & 3) * 2;
    float* outb = out + (size_t)b * (COUT*(size_t)NT);
    #pragma unroll
    for (int mi = 0; mi < 2; mi++)
        #pragma unroll
        for (int rr = 0; rr < 2; rr++) {
            const int o = (wm*2 + mi)*16 + g + rr*8;
            const float bv = __ldg(bias + o);
            #pragma unroll
            for (int ni = 0; ni < 4; ni++) {
                const int pos = p0 + wn*32 + ni*8 + c2;
                float2 r;
                r.x = acc[mi][ni][rr*2]   + bv;
                r.y = acc[mi][ni][rr*2+1] + bv;
                *(float2*)(outb + (size_t)o*NT + pos) = r;
            }
        }
}

// ---------------------------------------------------------------------------
extern "C" void kernel_launch(void* const* d_in, const int* in_sizes, int n_in,
                              void* d_out, int out_size)
{
    const float* x    = (const float*)d_in[0];
    const float* adj  = (const float*)d_in[1];
    const float* W    = (const float*)d_in[2];
    const float* bias = (const float*)d_in[3];
    float* out = (float*)d_out;

    cudaFuncSetAttribute(k_node_hmma, cudaFuncAttributeMaxDynamicSharedMemorySize,
                         NODE_SMEM);
    cudaFuncSetAttribute(k_chan_hmma, cudaFuncAttributeMaxDynamicSharedMemorySize,
                         CHAN_SMEM);

    k_prep_w<<<(COUT*SW + 255)/256, 256>>>(W);
    k_prep_adj<<<(MPAD*SA + 255)/256, 256>>>(adj);
    k_node_hmma<<<BATCH*CIN, 256, NODE_SMEM>>>(x);
    dim3 cgrid(NT/PTILE, BATCH);    // (85, 32)
    k_chan_hmma<<<cgrid, 256, CHAN_SMEM>>>(x, bias, out);
}

// round 11
// speedup vs baseline: 2.2446x; 1.2398x over previous
#include <cuda_runtime.h>
#include <cuda_bf16.h>
#include <cstdint>

#define NNODE 170
#define MPAD  176          // node dim padded to 11 m-tiles of 16
#define SA    184          // adj smem row stride (elems)
#define SB    72           // X/Y1 smem row stride (elems)
#define TSEQ  64
#define CIN   64
#define COUT  64
#define BATCH 32
#define NT    (NNODE*TSEQ)          // 10880 = 85 * 128
#define BSTRIDE (CIN*NT)
#define NITEMS (BATCH*CIN)          // 2048
#define NODE_GRID 148

#define KCH   192          // channel-stage K = 3*CIN
#define SW    200          // W image row stride (elems)
#define SC    136          // chan B tile row stride (elems)
#define PTILE 128          // pos per chan CTA

typedef unsigned long long u64;

// ---------------- device scratch (no allocs allowed) -----------------------
__device__ float g_Y1[BATCH*CIN*NT];
__device__ float g_Y2[BATCH*CIN*NT];
__device__ __align__(16) __nv_bfloat16 g_adjh[MPAD*SA]; // padded [176][184]
__device__ __align__(16) __nv_bfloat16 g_adjl[MPAD*SA];
__device__ __align__(16) __nv_bfloat16 g_Wh[COUT*SW];   // [o][k=s*64+c] hi
__device__ __align__(16) __nv_bfloat16 g_Wl[COUT*SW];   // lo

// ---------------- node smem map (bytes) -------------------------------------
#define AH_OFF 0                        // 176*184*2 = 64768
#define AL_OFF 64768
#define BH_OFF 129536                   // 176*72*2  = 25344
#define BL_OFF 154880
#define NODE_SMEM 180224

// ---------------- chan smem map (bytes) -------------------------------------
#define WH_OFF 0                        // 64*200*2 = 25600
#define WL_OFF 25600
#define CBH_OFF 51200                   // 192*136*2 = 52224
#define CBL_OFF 103424
#define CHAN_SMEM 155648

// ---------------- helpers ---------------------------------------------------
__device__ __forceinline__ uint32_t smem_u32(const void* p) {
    uint32_t a;
    asm("{ .reg .u64 t; cvta.to.shared.u64 t, %1; cvt.u32.u64 %0, t; }"
        : "=r"(a) : "l"(p));
    return a;
}

#define LDSM_X4(r, addr) \
    asm volatile("ldmatrix.sync.aligned.m8n8.x4.shared.b16 {%0,%1,%2,%3}, [%4];" \
        : "=r"((r)[0]), "=r"((r)[1]), "=r"((r)[2]), "=r"((r)[3]) : "r"(addr))
#define LDSM_X4T(r, addr) \
    asm volatile("ldmatrix.sync.aligned.m8n8.x4.trans.shared.b16 {%0,%1,%2,%3}, [%4];" \
        : "=r"((r)[0]), "=r"((r)[1]), "=r"((r)[2]), "=r"((r)[3]) : "r"(addr))

#define MMA_BF16(d, a, b0, b1) \
    asm volatile("mma.sync.aligned.m16n8k16.row.col.f32.bf16.bf16.f32 " \
        "{%0,%1,%2,%3}, {%4,%5,%6,%7}, {%8,%9}, {%0,%1,%2,%3};" \
        : "+f"((d)[0]), "+f"((d)[1]), "+f"((d)[2]), "+f"((d)[3]) \
        : "r"((a)[0]), "r"((a)[1]), "r"((a)[2]), "r"((a)[3]), "r"(b0), "r"(b1))

__device__ __forceinline__ void split_bf16(float v, __nv_bfloat16& h, __nv_bfloat16& l) {
    h = __float2bfloat16(v);
    l = __float2bfloat16(v - __bfloat162float(h));
}

// ---------------------------------------------------------------------------
// Prep kernels
// ---------------------------------------------------------------------------
__global__ void k_prep_w(const float* __restrict__ W)
{
    int i = blockIdx.x * 256 + threadIdx.x;     // over 64*SW
    if (i >= COUT*SW) return;
    int o = i / SW, k = i % SW;
    float v = 0.0f;
    if (k < KCH) {
        int s = k >> 6, c = k & 63;
        v = W[o*KCH + c*3 + s];
    }
    __nv_bfloat16 h, l;
    split_bf16(v, h, l);
    g_Wh[i] = h;
    g_Wl[i] = l;
}

__global__ void k_prep_adj(const float* __restrict__ adj)
{
    int i = blockIdx.x * 256 + threadIdx.x;
    if (i >= MPAD*SA) return;
    int q = i / SA, k = i % SA;
    float a = (q < NNODE && k < NNODE) ? adj[q*NNODE + k] : 0.0f;
    __nv_bfloat16 h, l;
    split_bf16(a, h, l);
    g_adjh[i] = h;
    g_adjl[i] = l;
}

// ---------------------------------------------------------------------------
// Node GEMM (512-thread version): warp w owns units (mtA, nh) and, for w<6,
// (mtB = 8 + (w>>1), nh). Both units share the same 32-col n-half -> B
// fragments loaded once. acc[u][nt][4], nt = col8 within the 32-col half.
// ---------------------------------------------------------------------------
__device__ __forceinline__ void gemm512(uint32_t aH, uint32_t aL,
                                        uint32_t bH, uint32_t bL,
                                        int w, int lane, float acc[2][4][4])
{
    #pragma unroll
    for (int u = 0; u < 2; u++)
        #pragma unroll
        for (int n = 0; n < 4; n++)
            #pragma unroll
            for (int p = 0; p < 4; p++) acc[u][n][p] = 0.0f;

    const int nh   = w & 1;
    const int mtA  = w >> 1;
    const bool hasB = (w < 6);
    const int mtB  = 8 + (w >> 1);
    const int brow = lane & 15;
    const int bcol = (lane >> 4) * 8;

    for (int k0 = 0; k0 < MPAD; k0 += 16) {
        uint32_t bh[2][4], bl[2][4];
        #pragma unroll
        for (int gB = 0; gB < 2; gB++) {
            const uint32_t bb =
                (uint32_t)((k0 + brow)*SB + nh*32 + gB*16 + bcol) * 2;
            LDSM_X4T(bh[gB], bH + bb);
            LDSM_X4T(bl[gB], bL + bb);
        }
        uint32_t ah[4], al[4];
        const uint32_t abA = (uint32_t)((mtA*16 + brow)*SA + k0 + bcol) * 2;
        LDSM_X4(ah, aH + abA);
        LDSM_X4(al, aL + abA);
        #pragma unroll
        for (int gB = 0; gB < 2; gB++)
            #pragma unroll
            for (int s = 0; s < 2; s++) {
                float* d = acc[0][gB*2 + s];
                MMA_BF16(d, ah, bh[gB][s*2], bh[gB][s*2+1]);
                MMA_BF16(d, ah, bl[gB][s*2], bl[gB][s*2+1]);
                MMA_BF16(d, al, bh[gB][s*2], bh[gB][s*2+1]);
            }
        if (hasB) {
            uint32_t ah2[4], al2[4];
            const uint32_t abB = (uint32_t)((mtB*16 + brow)*SA + k0 + bcol) * 2;
            LDSM_X4(ah2, aH + abB);
            LDSM_X4(al2, aL + abB);
            #pragma unroll
            for (int gB = 0; gB < 2; gB++)
                #pragma unroll
                for (int s = 0; s < 2; s++) {
                    float* d = acc[1][gB*2 + s];
                    MMA_BF16(d, ah2, bh[gB][s*2], bh[gB][s*2+1]);
                    MMA_BF16(d, ah2, bl[gB][s*2], bl[gB][s*2+1]);
                    MMA_BF16(d, al2, bh[gB][s*2], bh[gB][s*2+1]);
                }
        }
    }
}

// ---------------------------------------------------------------------------
// Persistent node stage: grid=148 CTAs x 512 threads; adj staged ONCE per CTA,
// then loop over (b,c) items:  Y1 = adj @ X ;  Y2 = 2*adj @ Y1 - X
// ---------------------------------------------------------------------------
__global__ __launch_bounds__(512, 1) void k_node_pers(const float* __restrict__ x)
{
    extern __shared__ char smem[];
    const uint32_t sbase = smem_u32(smem);
    const uint32_t aH = sbase + AH_OFF, aL = sbase + AL_OFF;
    const uint32_t bHo = sbase + BH_OFF, bLo = sbase + BL_OFF;
    __nv_bfloat16* sBH = (__nv_bfloat16*)(smem + BH_OFF);
    __nv_bfloat16* sBL = (__nv_bfloat16*)(smem + BL_OFF);

    const int tid  = threadIdx.x;
    const int w    = tid >> 5;
    const int lane = tid & 31;
    const int g    = lane >> 2;
    const int c2   = (lane & 3) * 2;
    const int nh   = w & 1;

    // ---- stage adj hi/lo once ----
    {
        const float4* gh = (const float4*)g_adjh;
        const float4* gl = (const float4*)g_adjl;
        float4* dh = (float4*)(smem + AH_OFF);
        float4* dl = (float4*)(smem + AL_OFF);
        for (int i = tid; i < (MPAD*SA*2)/16; i += 512) { dh[i] = gh[i]; dl[i] = gl[i]; }
    }
    // zero B pad rows once (epilogue-1 re-zeros them every item)
    for (int i = tid; i < (MPAD - NNODE)*SB; i += 512) {
        const int idx = NNODE*SB + i;
        sBH[idx] = __float2bfloat16(0.f);
        sBL[idx] = __float2bfloat16(0.f);
    }

    float acc[2][4][4];

    for (int it = blockIdx.x; it < NITEMS; it += NODE_GRID) {
        const float* Xg = x + (size_t)it * NT;
        float* Y1g = g_Y1 + (size_t)it * NT;
        float* Y2g = g_Y2 + (size_t)it * NT;

        __syncthreads();     // prior GEMM2 readers done before B overwrite
        // ---- stage X hi/lo (float4 along t) ----
        for (int idx = tid; idx < NNODE*(TSEQ/4); idx += 512) {
            const int n  = idx >> 4;
            const int t4 = idx & 15;
            const float4 v = __ldg((const float4*)(Xg + n*TSEQ) + t4);
            __nv_bfloat16 h0,l0,h1,l1,h2,l2,h3,l3;
            split_bf16(v.x, h0, l0); split_bf16(v.y, h1, l1);
            split_bf16(v.z, h2, l2); split_bf16(v.w, h3, l3);
            __nv_bfloat162 hh[2] = { {h0,h1}, {h2,h3} };
            __nv_bfloat162 ll[2] = { {l0,l1}, {l2,l3} };
            *(uint2*)(sBH + n*SB + t4*4) = *(uint2*)hh;
            *(uint2*)(sBL + n*SB + t4*4) = *(uint2*)ll;
        }
        __syncthreads();

        // ======== GEMM 1: Y1 = adj @ X ========
        gemm512(aH, aL, bHo, bLo, w, lane, acc);
        __syncthreads();     // everyone done reading B

        // epilogue 1: write Y1 f32 + resplit into B
        #pragma unroll
        for (int u = 0; u < 2; u++) {
            const int mt = u ? 8 + (w >> 1) : (w >> 1);
            if (u == 0 || w < 6) {
                #pragma unroll
                for (int nt = 0; nt < 4; nt++) {
                    const int t = nh*32 + nt*8 + c2;
                    #pragma unroll
                    for (int rr = 0; rr < 2; rr++) {
                        const int q = mt*16 + g + rr*8;
                        const float v0 = acc[u][nt][rr*2];
                        const float v1 = acc[u][nt][rr*2+1];
                        if (q < NNODE) {
                            float2 o; o.x = v0; o.y = v1;
                            *(float2*)(Y1g + q*TSEQ + t) = o;
                        }
                        __nv_bfloat162 h2, l2;
                        split_bf16(v0, h2.x, l2.x);
                        split_bf16(v1, h2.y, l2.y);
                        *(__nv_bfloat162*)(sBH + q*SB + t) = h2;
                        *(__nv_bfloat162*)(sBL + q*SB + t) = l2;
                    }
                }
            }
        }
        __syncthreads();

        // ======== GEMM 2: Y2 = 2*adj @ Y1 - X ========
        gemm512(aH, aL, bHo, bLo, w, lane, acc);

        #pragma unroll
        for (int u = 0; u < 2; u++) {
            const int mt = u ? 8 + (w >> 1) : (w >> 1);
            if (u == 0 || w < 6) {
                #pragma unroll
                for (int nt = 0; nt < 4; nt++) {
                    const int t = nh*32 + nt*8 + c2;
                    #pragma unroll
                    for (int rr = 0; rr < 2; rr++) {
                        const int q = mt*16 + g + rr*8;
                        if (q < NNODE) {
                            const float2 xv = *(const float2*)(Xg + q*TSEQ + t);
                            float2 o;
                            o.x = 2.f*acc[u][nt][rr*2]   - xv.x;
                            o.y = 2.f*acc[u][nt][rr*2+1] - xv.y;
                            *(float2*)(Y2g + q*TSEQ + t) = o;
                        }
                    }
                }
            }
        }
    }
}

// ---------------------------------------------------------------------------
// Channel stage via HMMA (unchanged from R8)
// ---------------------------------------------------------------------------
__global__ __launch_bounds__(256, 1) void k_chan_hmma(const float* __restrict__ x,
                                                      const float* __restrict__ bias,
                                                      float* __restrict__ out)
{
    extern __shared__ char smem[];
    const uint32_t sbase = smem_u32(smem);
    const uint32_t wH = sbase + WH_OFF, wL = sbase + WL_OFF;
    const uint32_t cH = sbase + CBH_OFF, cL = sbase + CBL_OFF;
    __nv_bfloat16* sBH = (__nv_bfloat16*)(smem + CBH_OFF);
    __nv_bfloat16* sBL = (__nv_bfloat16*)(smem + CBL_OFF);

    const int tid  = threadIdx.x;
    const int w    = tid >> 5;
    const int lane = tid & 31;
    const int wm   = w & 1;
    const int wn   = w >> 1;
    const int b    = blockIdx.y;
    const int p0   = blockIdx.x * PTILE;

    const float* srcs[3];
    srcs[0] = x    + (size_t)b * BSTRIDE;
    srcs[1] = g_Y1 + (size_t)b * BSTRIDE;
    srcs[2] = g_Y2 + (size_t)b * BSTRIDE;

    {
        const float4* gh = (const float4*)g_Wh;
        const float4* gl = (const float4*)g_Wl;
        float4* dh = (float4*)(smem + WH_OFF);
        float4* dl = (float4*)(smem + WL_OFF);
        for (int i = tid; i < (COUT*SW*2)/16; i += 256) { dh[i] = gh[i]; dl[i] = gl[i]; }
    }
    for (int idx = tid; idx < KCH*(PTILE/4); idx += 256) {
        const int k  = idx >> 5;
        const int p4 = idx & 31;
        const float4 v = *(const float4*)(srcs[k >> 6] + (size_t)(k & 63)*NT + p0 + p4*4);
        __nv_bfloat16 h0,l0,h1,l1,h2,l2,h3,l3;
        split_bf16(v.x, h0, l0); split_bf16(v.y, h1, l1);
        split_bf16(v.z, h2, l2); split_bf16(v.w, h3, l3);
        __nv_bfloat162 hh[2] = { {h0,h1}, {h2,h3} };
        __nv_bfloat162 ll[2] = { {l0,l1}, {l2,l3} };
        *(uint2*)(sBH + k*SC + p4*4) = *(uint2*)hh;
        *(uint2*)(sBL + k*SC + p4*4) = *(uint2*)ll;
    }
    __syncthreads();

    float acc[2][4][4];
    #pragma unroll
    for (int mi = 0; mi < 2; mi++)
        #pragma unroll
        for (int ni = 0; ni < 4; ni++)
            #pragma unroll
            for (int p = 0; p < 4; p++) acc[mi][ni][p] = 0.0f;

    const int brow_l = lane & 15;
    const int bcol_l = (lane >> 4) * 8;

    for (int k0 = 0; k0 < KCH; k0 += 16) {
        uint32_t bh[2][4], bl[2][4];
        #pragma unroll
        for (int gB = 0; gB < 2; gB++) {
            const uint32_t bb =
                (uint32_t)((k0 + brow_l)*SC + wn*32 + gB*16 + bcol_l) * 2;
            LDSM_X4T(bh[gB], cH + bb);
            LDSM_X4T(bl[gB], cL + bb);
        }
        #pragma unroll
        for (int mi = 0; mi < 2; mi++) {
            uint32_t ah[4], al[4];
            const uint32_t ab =
                (uint32_t)(((wm*2 + mi)*16 + brow_l)*SW + k0 + bcol_l) * 2;
            LDSM_X4(ah, wH + ab);
            LDSM_X4(al, wL + ab);
            #pragma unroll
            for (int gB = 0; gB < 2; gB++)
                #pragma unroll
                for (int s = 0; s < 2; s++) {
                    float* d = acc[mi][gB*2 + s];
                    MMA_BF16(d, ah, bh[gB][s*2], bh[gB][s*2+1]);
                    MMA_BF16(d, ah, bl[gB][s*2], bl[gB][s*2+1]);
                    MMA_BF16(d, al, bh[gB][s*2], bh[gB][s*2+1]);
                }
        }
    }

    const int g  = lane >> 2;
    const int c2 = (lane & 3) * 2;
    float* outb = out + (size_t)b * (COUT*(size_t)NT);
    #pragma unroll
    for (int mi = 0; mi < 2; mi++)
        #pragma unroll
        for (int rr = 0; rr < 2; rr++) {
            const int o = (wm*2 + mi)*16 + g + rr*8;
            const float bv = __ldg(bias + o);
            #pragma unroll
            for (int ni = 0; ni < 4; ni++) {
                const int pos = p0 + wn*32 + ni*8 + c2;
                float2 r;
                r.x = acc[mi][ni][rr*2]   + bv;
                r.y = acc[mi][ni][rr*2+1] + bv;
                *(float2*)(outb + (size_t)o*NT + pos) = r;
            }
        }
}

// ---------------------------------------------------------------------------
extern "C" void kernel_launch(void* const* d_in, const int* in_sizes, int n_in,
                              void* d_out, int out_size)
{
    const float* x    = (const float*)d_in[0];
    const float* adj  = (const float*)d_in[1];
    const float* W    = (const float*)d_in[2];
    const float* bias = (const float*)d_in[3];
    float* out = (float*)d_out;

    cudaFuncSetAttribute(k_node_pers, cudaFuncAttributeMaxDynamicSharedMemorySize,
                         NODE_SMEM);
    cudaFuncSetAttribute(k_chan_hmma, cudaFuncAttributeMaxDynamicSharedMemorySize,
                         CHAN_SMEM);

    k_prep_w<<<(COUT*SW + 255)/256, 256>>>(W);
    k_prep_adj<<<(MPAD*SA + 255)/256, 256>>>(adj);
    k_node_pers<<<NODE_GRID, 512, NODE_SMEM>>>(x);
    dim3 cgrid(NT/PTILE, BATCH);    // (85, 32)
    k_chan_hmma<<<cgrid, 256, CHAN_SMEM>>>(x, bias, out);
}